// round 6
// baseline (speedup 1.0000x reference)
#include <cuda_runtime.h>
#include <cstdint>
#include <math.h>

// ============================================================================
// ProbSparse attention: B=4,H=8,T=12,N=325,D=64, FACTOR=5 -> U=30
// out[b,n,t,h*64+d] = ctx[b,h,t,n,d]
// K row-major + V TRANSPOSED in SMEM; e-values staged in SMEM; phase-8 GEMV
// fully vectorized (float4 both sides, no shfl).
// ============================================================================

#define Bc 4
#define Hc 8
#define Tc 12
#define Nc 325
#define Dc 64
#define Uc 30
#define Gc (Bc*Hc*Tc)      // 384 groups
#define NT 480             // threads per block (15 warps)
#define NW 15
#define KVS 68             // K row stride (floats)
#define VTS 332            // V^T row stride: mult of 4, ≡12 mod 32 -> conflict-free f4
#define SCS 328            // e-value row stride
#define NSTEP 11           // ceil(325/32)
#define NPASS 6            // ceil(325/60) query passes in phase 2

// ---------------- shared memory layout (float offsets) ----------------
#define OFF_K    0                         // 325*68  = 22100
#define OFF_VT   (Nc*KVS)                  // 64*332  = 21248
#define OFF_M    (OFF_VT + Dc*VTS)         // 328
#define OFF_S    (OFF_M + 328)             // 30*328  = 9840
#define OFF_Q    (OFF_S + Uc*SCS)          // 1920
#define OFF_UPD  (OFF_Q + Uc*Dc)           // 1920
#define OFF_MEAN (OFF_UPD + Uc*Dc)         // 64
#define OFF_SEL  (OFF_MEAN + 64)           // 32
#define OFF_RANK (OFF_SEL + 32)            // 328
#define SMEM_FLOATS (OFF_RANK + 328)       // 57780
#define SMEM_BYTES (SMEM_FLOATS * 4)       // 231120 B (<= 232448 max/CTA)

__device__ int g_idx[Nc * Uc];

// ---------------- threefry2x32 (exact JAX schedule) ----------------
__device__ __forceinline__ uint32_t rotl32(uint32_t x, int r) {
    return (x << r) | (x >> (32 - r));
}

__device__ __forceinline__ void tf2x32(uint32_t k0, uint32_t k1,
                                       uint32_t x0, uint32_t x1,
                                       uint32_t& o0, uint32_t& o1) {
    uint32_t ks2 = k0 ^ k1 ^ 0x1BD11BDAu;
    x0 += k0; x1 += k1;
#define TF_R(r) { x0 += x1; x1 = rotl32(x1, r); x1 ^= x0; }
    TF_R(13) TF_R(15) TF_R(26) TF_R(6)   x0 += k1;  x1 += ks2 + 1u;
    TF_R(17) TF_R(29) TF_R(16) TF_R(24)  x0 += ks2; x1 += k0  + 2u;
    TF_R(13) TF_R(15) TF_R(26) TF_R(6)   x0 += k0;  x1 += k1  + 3u;
    TF_R(17) TF_R(29) TF_R(16) TF_R(24)  x0 += k1;  x1 += ks2 + 4u;
    TF_R(13) TF_R(15) TF_R(26) TF_R(6)   x0 += ks2; x1 += k0  + 5u;
#undef TF_R
    o0 = x0; o1 = x1;
}

// idx_sample = jax.random.randint(key(42), (325,30), 0, 325)  [verified bit-exact]
__global__ void idx_kernel() {
    int j = blockIdx.x * blockDim.x + threadIdx.x;
    if (j >= Nc * Uc) return;
    const uint32_t SPAN = 325u;
    const uint32_t MULT = 321u;  // (2^32) mod 325
    uint32_t a0, a1, b0, b1;
    tf2x32(0u, 42u, 0u, 0u, a0, a1);
    tf2x32(0u, 42u, 0u, 1u, b0, b1);
    uint32_t h0, h1, l0, l1;
    tf2x32(a0, a1, 0u, (uint32_t)j, h0, h1);
    uint32_t hi = h0 ^ h1;
    tf2x32(b0, b1, 0u, (uint32_t)j, l0, l1);
    uint32_t lo = l0 ^ l1;
    g_idx[j] = (int)(((hi % SPAN) * MULT + (lo % SPAN)) % SPAN);
}

__device__ __forceinline__ float dot4(float4 a, float4 b) {
    return a.x * b.x + a.y * b.y + a.z * b.z + a.w * b.w;
}

__device__ __forceinline__ void cp_async16(uint32_t dst, const void* src) {
    asm volatile("cp.async.cg.shared.global [%0], [%1], 16;\n"
                 :: "r"(dst), "l"(src));
}

// ---------------- main fused kernel: one block per (b,h,t) group ----------------
__global__ __launch_bounds__(NT, 1)
void probsparse_kernel(const float* __restrict__ Q,
                       const float* __restrict__ K,
                       const float* __restrict__ V,
                       float* __restrict__ out) {
    extern __shared__ float sm[];
    float* sK    = sm + OFF_K;
    float* sVT   = sm + OFF_VT;
    float* sM    = sm + OFF_M;
    float* sS    = sm + OFF_S;
    float* sQ    = sm + OFF_Q;
    float* sUpd  = sm + OFF_UPD;
    float* sMean = sm + OFF_MEAN;
    int*   sSel  = (int*)(sm + OFF_SEL);
    int*   sRank = (int*)(sm + OFF_RANK);

    const int g    = blockIdx.x;
    const int tid  = threadIdx.x;
    const int lane = tid & 31;
    const int warp = tid >> 5;
    const size_t base = (size_t)g * Nc * Dc;

    // ---- phase 1: K via cp.async; V loaded TRANSPOSED via LDG+STS ----
    {
        uint32_t sb = (uint32_t)__cvta_generic_to_shared(sm);
        const float4* K4 = (const float4*)(K + base);
        for (int i = tid; i < Nc * Dc / 4; i += NT) {
            int n = i >> 4, d4 = i & 15;
            cp_async16(sb + (uint32_t)(OFF_K + n * KVS + d4 * 4) * 4u, K4 + i);
        }
        asm volatile("cp.async.commit_group;\n");
        // V transpose: coalesced global reads, 4-way-conflict SMEM writes (once)
        const float* Vg = V + base;
        for (int i = tid; i < Nc * Dc; i += NT) {
            int n = i >> 6, d = i & 63;
            sVT[d * VTS + n] = Vg[i];
        }
        if (tid < Dc) {   // zero pad cols 325..327 (read by f4 tail, e=0 there)
            sVT[tid * VTS + 325] = 0.f;
            sVT[tid * VTS + 326] = 0.f;
            sVT[tid * VTS + 327] = 0.f;
        }
        for (int i = tid; i < Nc; i += NT) sRank[i] = -1;
        asm volatile("cp.async.wait_group 0;\n" ::: "memory");
    }
    __syncthreads();

    // ========================================================================
    // phase 2: sparsity measure M[n] = max_u(qk) - mean_u(qk).
    // 8-lane subgroup per query: conflict-free 128B row gathers + 3 shfl.
    // ========================================================================
    {
        const int sub = lane >> 3;     // query slot 0..3 within warp
        const int sl  = lane & 7;      // lane within subgroup
#pragma unroll 1
        for (int p = 0; p < NPASS; p++) {
            int n = p * 60 + warp * 4 + sub;
            bool act = n < Nc;
            int nn = act ? n : Nc - 1;
            const float4* qr = (const float4*)(Q + base + (size_t)nn * Dc + sl * 8);
            float4 qA = qr[0], qB = qr[1];
            const int* idxp = g_idx + nn * Uc;
            float mx = -INFINITY, sum = 0.f;
            int kn0 = idxp[0], kn1 = idxp[1];
#pragma unroll
            for (int u = 0; u < Uc; u += 2) {
                int knA = kn0, knB = kn1;
                if (u + 2 < Uc) { kn0 = idxp[u + 2]; kn1 = idxp[u + 3]; }
                const float4* krA = (const float4*)&sK[knA * KVS + sl * 8];
                const float4* krB = (const float4*)&sK[knB * KVS + sl * 8];
                float pa = dot4(qA, krA[0]) + dot4(qB, krA[1]);
                float pb = dot4(qA, krB[0]) + dot4(qB, krB[1]);
                pa += __shfl_xor_sync(0xffffffffu, pa, 1);
                pb += __shfl_xor_sync(0xffffffffu, pb, 1);
                pa += __shfl_xor_sync(0xffffffffu, pa, 2);
                pb += __shfl_xor_sync(0xffffffffu, pb, 2);
                pa += __shfl_xor_sync(0xffffffffu, pa, 4);
                pb += __shfl_xor_sync(0xffffffffu, pb, 4);
                mx = fmaxf(mx, fmaxf(pa, pb));
                sum += pa + pb;
            }
            if (act && sl == 0) sM[n] = mx - sum * (1.0f / Uc);
        }
    }
    __syncthreads();

    // ---- phase 3: top-30 via parallel rank counting (ties -> lowest index) ----
    if (tid < Nc) {
        float mi = sM[tid];
        int rank = 0;
        for (int j = 0; j < Nc; j++) {
            float mj = sM[j];   // broadcast read
            rank += (mj > mi) || (mj == mi && j < tid) ? 1 : 0;
        }
        if (rank < Uc) { sRank[tid] = rank; sSel[rank] = tid; }
    }
    __syncthreads();

    // ---- phase 4: gather selected queries ----
    for (int i = tid; i < Uc * Dc; i += NT) {
        int u = i >> 6, d = i & 63;
        sQ[u * Dc + d] = Q[base + (size_t)sSel[u] * Dc + d];
    }
    __syncthreads();

    // ---- column mean of V from V^T (warps 0-1, conflict-free float4) ----
    if (tid < Dc) {
        const float* vr = &sVT[tid * VTS];
        float s0 = 0.f, s1 = 0.f, s2 = 0.f, s3 = 0.f;
        for (int n = 0; n < 324; n += 4) {
            float4 v = *(const float4*)&vr[n];
            s0 += v.x; s1 += v.y; s2 += v.z; s3 += v.w;
        }
        sMean[tid] = ((s0 + s1) + (s2 + s3) + vr[324]) * (1.0f / Nc);
    }

    // ---- phase 5+8 fused (barrier-free per warp): scores -> softmax -> GEMV ----
    {
        const int u0 = warp, u1 = warp + NW;
        const int half = lane >> 4;         // 0 or 1
        const int lsub = lane & 15;
        const int d0 = half << 5;           // 0 or 32

        float4 qa[8], qb[8];
        const float4* qa4 = (const float4*)&sQ[u0 * Dc + d0];
        const float4* qb4 = (const float4*)&sQ[u1 * Dc + d0];
#pragma unroll
        for (int j = 0; j < 8; j++) { qa[j] = qa4[j]; qb[j] = qb4[j]; }

        // --- scores: lane pairs (l, l+16) split d; each K row read once/warp ---
        float e0r[NSTEP], e1r[NSTEP];
        float lmax0 = -INFINITY, lmax1 = -INFINITY;
#pragma unroll
        for (int t = 0; t < NSTEP; t++) {
            int bn  = t * 32;
            int alo = min(bn + lsub,      Nc - 1) * KVS + d0;
            int ahi = min(bn + 16 + lsub, Nc - 1) * KVS + d0;
            const float4* klo = (const float4*)&sK[alo];
            const float4* khi = (const float4*)&sK[ahi];
            float p00 = 0.f, p01 = 0.f, p10 = 0.f, p11 = 0.f;
#pragma unroll
            for (int j = 0; j < 8; j++) {
                float4 kl = klo[j], kh = khi[j];
                p00 += dot4(qa[j], kl);
                p01 += dot4(qb[j], kl);
                p10 += dot4(qa[j], kh);
                p11 += dot4(qb[j], kh);
            }
            p00 += __shfl_xor_sync(0xffffffffu, p00, 16);
            p01 += __shfl_xor_sync(0xffffffffu, p01, 16);
            p10 += __shfl_xor_sync(0xffffffffu, p10, 16);
            p11 += __shfl_xor_sync(0xffffffffu, p11, 16);
            int n = bn + lane;
            float s0 = (half ? p10 : p00) * 0.125f;
            float s1 = (half ? p11 : p01) * 0.125f;
            bool ok = (n < Nc);
            e0r[t] = s0; e1r[t] = s1;
            lmax0 = fmaxf(lmax0, ok ? s0 : -INFINITY);
            lmax1 = fmaxf(lmax1, ok ? s1 : -INFINITY);
        }
#pragma unroll
        for (int o = 16; o > 0; o >>= 1) {
            lmax0 = fmaxf(lmax0, __shfl_xor_sync(0xffffffffu, lmax0, o));
            lmax1 = fmaxf(lmax1, __shfl_xor_sync(0xffffffffu, lmax1, o));
        }
        // --- exp + stage e-values to SMEM (own rows; zero beyond Nc) ---
        float lsum0 = 0.f, lsum1 = 0.f;
#pragma unroll
        for (int t = 0; t < NSTEP; t++) {
            int n = t * 32 + lane;
            bool ok = n < Nc;
            float e0 = ok ? __expf(e0r[t] - lmax0) : 0.f;
            float e1 = ok ? __expf(e1r[t] - lmax1) : 0.f;
            lsum0 += e0; lsum1 += e1;
            if (n < SCS) {
                sS[u0 * SCS + n] = e0;
                sS[u1 * SCS + n] = e1;
            }
        }
#pragma unroll
        for (int o = 16; o > 0; o >>= 1) {
            lsum0 += __shfl_xor_sync(0xffffffffu, lsum0, o);
            lsum1 += __shfl_xor_sync(0xffffffffu, lsum1, o);
        }
        float inv0 = 1.0f / lsum0;
        float inv1 = 1.0f / lsum1;

        // --- GEMV vs V^T: all-float4, conflict-free, zero shfl ---
        float a00 = 0.f, a01 = 0.f, a10 = 0.f, a11 = 0.f;
        const float* e0p = &sS[u0 * SCS];
        const float* e1p = &sS[u1 * SCS];
        const float* vt0 = &sVT[lane * VTS];
        const float* vt1 = &sVT[(lane + 32) * VTS];
#pragma unroll 2
        for (int n = 0; n < SCS; n += 4) {
            float4 e0 = *(const float4*)&e0p[n];
            float4 e1 = *(const float4*)&e1p[n];
            float4 v0 = *(const float4*)&vt0[n];
            float4 v1 = *(const float4*)&vt1[n];
            a00 += e0.x * v0.x + e0.y * v0.y + e0.z * v0.z + e0.w * v0.w;
            a01 += e0.x * v1.x + e0.y * v1.y + e0.z * v1.z + e0.w * v1.w;
            a10 += e1.x * v0.x + e1.y * v0.y + e1.z * v0.z + e1.w * v0.w;
            a11 += e1.x * v1.x + e1.y * v1.y + e1.z * v1.z + e1.w * v1.w;
        }
        sUpd[u0 * Dc + lane]      = a00 * inv0;
        sUpd[u0 * Dc + lane + 32] = a01 * inv0;
        sUpd[u1 * Dc + lane]      = a10 * inv1;
        sUpd[u1 * Dc + lane + 32] = a11 * inv1;
    }
    __syncthreads();

    // ---- phase 9: write output (selected -> attention, else column mean) ----
    {
        const int b = g / (Hc * Tc);
        const int h = (g / Tc) % Hc;
        const int t = g % Tc;
        for (int i = tid; i < Nc * Dc / 4; i += NT) {
            int n = i >> 4, d4 = (i & 15) * 4;
            int r = sRank[n];
            float4 v = (r >= 0) ? *(float4*)&sUpd[r * Dc + d4]
                                : *(float4*)&sMean[d4];
            size_t o = ((size_t)(b * Nc + n) * Tc + t) * (size_t)(Hc * Dc)
                     + h * Dc + d4;
            *(float4*)&out[o] = v;
        }
    }
}

// ---------------- launch ----------------
extern "C" void kernel_launch(void* const* d_in, const int* in_sizes, int n_in,
                              void* d_out, int out_size) {
    const float* Q = (const float*)d_in[0];
    const float* K = (const float*)d_in[1];
    const float* V = (const float*)d_in[2];
    float* out = (float*)d_out;

    cudaFuncSetAttribute(probsparse_kernel,
                         cudaFuncAttributeMaxDynamicSharedMemorySize, SMEM_BYTES);

    idx_kernel<<<(Nc * Uc + 255) / 256, 256>>>();
    probsparse_kernel<<<Gc, NT, SMEM_BYTES>>>(Q, K, V, out);
}

// round 8
// speedup vs baseline: 1.0900x; 1.0900x over previous
#include <cuda_runtime.h>
#include <cstdint>
#include <math.h>

// ============================================================================
// ProbSparse attention: B=4,H=8,T=12,N=325,D=64, FACTOR=5 -> U=30
// out[b,n,t,h*64+d] = ctx[b,h,t,n,d]
// K (stride 68) + V (stride 64) resident via cp.async. e-values staged in
// SMEM; P8 GEMV has zero shfl and writes selected rows straight to global.
// (Resubmission of round-7 kernel — prior bench died to a broker failure.)
// ============================================================================

#define Bc 4
#define Hc 8
#define Tc 12
#define Nc 325
#define Dc 64
#define Uc 30
#define Gc (Bc*Hc*Tc)      // 384 groups
#define NT 480             // threads per block (15 warps)
#define NW 15
#define KVS 68             // K row stride (bank-staggered for P5)
#define VS  64             // V row stride (scalar access: no stagger needed)
#define SCS 328            // e-value row stride (f4-aligned, 325+pad)
#define NSTEP 11           // ceil(325/32)
#define NPASS 6            // ceil(325/60) query passes in phase 2

// ---------------- shared memory layout (float offsets) ----------------
#define OFF_K    0                        // 22100
#define OFF_V    22100                    // 20800
#define OFF_M    42900                    // 328
#define OFF_S    43228                    // 30*328 = 9840
#define OFF_Q    53068                    // 1920
#define OFF_MEAN 54988                    // 64
#define OFF_RED  55052                    // 1024
#define OFF_SEL  56076                    // 32
#define OFF_RANK 56108                    // 328
#define SMEM_FLOATS 56436
#define SMEM_BYTES (SMEM_FLOATS * 4)      // 225744 B <= 232448

__device__ int g_idx2[Nc * 32];           // padded to 32 ints/row for int4 loads

// ---------------- threefry2x32 (exact JAX schedule) ----------------
__device__ __forceinline__ uint32_t rotl32(uint32_t x, int r) {
    return (x << r) | (x >> (32 - r));
}

__device__ __forceinline__ void tf2x32(uint32_t k0, uint32_t k1,
                                       uint32_t x0, uint32_t x1,
                                       uint32_t& o0, uint32_t& o1) {
    uint32_t ks2 = k0 ^ k1 ^ 0x1BD11BDAu;
    x0 += k0; x1 += k1;
#define TF_R(r) { x0 += x1; x1 = rotl32(x1, r); x1 ^= x0; }
    TF_R(13) TF_R(15) TF_R(26) TF_R(6)   x0 += k1;  x1 += ks2 + 1u;
    TF_R(17) TF_R(29) TF_R(16) TF_R(24)  x0 += ks2; x1 += k0  + 2u;
    TF_R(13) TF_R(15) TF_R(26) TF_R(6)   x0 += k0;  x1 += k1  + 3u;
    TF_R(17) TF_R(29) TF_R(16) TF_R(24)  x0 += k1;  x1 += ks2 + 4u;
    TF_R(13) TF_R(15) TF_R(26) TF_R(6)   x0 += ks2; x1 += k0  + 5u;
#undef TF_R
    o0 = x0; o1 = x1;
}

// idx_sample = jax.random.randint(key(42), (325,30), 0, 325)  [verified bit-exact]
// stored padded: g_idx2[n*32 + u], u<30 real, u>=30 zero
__global__ void idx_kernel() {
    int j = blockIdx.x * blockDim.x + threadIdx.x;
    if (j >= Nc * 32) return;
    int n = j >> 5, u = j & 31;
    if (u >= Uc) { g_idx2[j] = 0; return; }
    int flat = n * Uc + u;
    const uint32_t SPAN = 325u;
    const uint32_t MULT = 321u;  // (2^32) mod 325
    uint32_t a0, a1, b0, b1;
    tf2x32(0u, 42u, 0u, 0u, a0, a1);
    tf2x32(0u, 42u, 0u, 1u, b0, b1);
    uint32_t h0, h1, l0, l1;
    tf2x32(a0, a1, 0u, (uint32_t)flat, h0, h1);
    uint32_t hi = h0 ^ h1;
    tf2x32(b0, b1, 0u, (uint32_t)flat, l0, l1);
    uint32_t lo = l0 ^ l1;
    g_idx2[j] = (int)(((hi % SPAN) * MULT + (lo % SPAN)) % SPAN);
}

__device__ __forceinline__ float dot4(float4 a, float4 b) {
    return a.x * b.x + a.y * b.y + a.z * b.z + a.w * b.w;
}

__device__ __forceinline__ void cp_async16(uint32_t dst, const void* src) {
    asm volatile("cp.async.cg.shared.global [%0], [%1], 16;\n"
                 :: "r"(dst), "l"(src));
}

// ---------------- main fused kernel: one block per (b,h,t) group ----------------
__global__ __launch_bounds__(NT, 1)
void probsparse_kernel(const float* __restrict__ Q,
                       const float* __restrict__ K,
                       const float* __restrict__ V,
                       float* __restrict__ out) {
    extern __shared__ float sm[];
    float* sK    = sm + OFF_K;
    float* sV    = sm + OFF_V;
    float* sM    = sm + OFF_M;
    float* sS    = sm + OFF_S;
    float* sQ    = sm + OFF_Q;
    float* sMean = sm + OFF_MEAN;
    float* sRed  = sm + OFF_RED;
    int*   sSel  = (int*)(sm + OFF_SEL);
    int*   sRank = (int*)(sm + OFF_RANK);

    const int g    = blockIdx.x;
    const int tid  = threadIdx.x;
    const int lane = tid & 31;
    const int warp = tid >> 5;
    const size_t base = (size_t)g * Nc * Dc;
    const int bb = g / (Hc * Tc);
    const int hh = (g / Tc) % Hc;
    const int tt = g % Tc;

    // ---- phase 1: stage K (stride 68) and V (stride 64) via cp.async ----
    {
        uint32_t sb = (uint32_t)__cvta_generic_to_shared(sm);
        const float4* K4 = (const float4*)(K + base);
        const float4* V4 = (const float4*)(V + base);
        for (int i = tid; i < Nc * Dc / 4; i += NT) {
            int n = i >> 4, d4 = i & 15;
            cp_async16(sb + (uint32_t)(OFF_K + n * KVS + d4 * 4) * 4u, K4 + i);
            cp_async16(sb + (uint32_t)(OFF_V) * 4u + (uint32_t)i * 16u, V4 + i);
        }
        asm volatile("cp.async.commit_group;\n");
        for (int i = tid; i < Nc; i += NT) sRank[i] = -1;
        asm volatile("cp.async.wait_group 0;\n" ::: "memory");
    }
    __syncthreads();

    // ========================================================================
    // phase 2: sparsity measure M[n] = max_u(qk) - mean_u(qk).
    // 8-lane subgroup per query; idx via int4 prefetch queue.
    // ========================================================================
    {
        const int sub = lane >> 3;     // query slot 0..3 within warp
        const int sl  = lane & 7;      // lane within subgroup
#pragma unroll 1
        for (int p = 0; p < NPASS; p++) {
            int n = p * 60 + warp * 4 + sub;
            bool act = n < Nc;
            int nn = act ? n : Nc - 1;
            const float4* qr = (const float4*)(Q + base + (size_t)nn * Dc + sl * 8);
            float4 qA = qr[0], qB = qr[1];
            const int4* idxp4 = (const int4*)(g_idx2 + nn * 32);
            float mx = -INFINITY, sum = 0.f;
            int4 A = idxp4[0], B = idxp4[1];
#pragma unroll
            for (int c = 0; c < 8; c++) {
                int kA = A.x, kB = A.y, kC = A.z, kD = A.w;
                A = B;
                if (c + 2 < 8) B = idxp4[c + 2];
                {   // pair 1
                    const float4* krA = (const float4*)&sK[kA * KVS + sl * 8];
                    const float4* krB = (const float4*)&sK[kB * KVS + sl * 8];
                    float pa = dot4(qA, krA[0]) + dot4(qB, krA[1]);
                    float pb = dot4(qA, krB[0]) + dot4(qB, krB[1]);
                    pa += __shfl_xor_sync(0xffffffffu, pa, 1);
                    pb += __shfl_xor_sync(0xffffffffu, pb, 1);
                    pa += __shfl_xor_sync(0xffffffffu, pa, 2);
                    pb += __shfl_xor_sync(0xffffffffu, pb, 2);
                    pa += __shfl_xor_sync(0xffffffffu, pa, 4);
                    pb += __shfl_xor_sync(0xffffffffu, pb, 4);
                    mx = fmaxf(mx, fmaxf(pa, pb));
                    sum += pa + pb;
                }
                if (c < 7) {   // pair 2 (chunk 7 holds only samples 28,29)
                    const float4* krC = (const float4*)&sK[kC * KVS + sl * 8];
                    const float4* krD = (const float4*)&sK[kD * KVS + sl * 8];
                    float pc = dot4(qA, krC[0]) + dot4(qB, krC[1]);
                    float pd = dot4(qA, krD[0]) + dot4(qB, krD[1]);
                    pc += __shfl_xor_sync(0xffffffffu, pc, 1);
                    pd += __shfl_xor_sync(0xffffffffu, pd, 1);
                    pc += __shfl_xor_sync(0xffffffffu, pc, 2);
                    pd += __shfl_xor_sync(0xffffffffu, pd, 2);
                    pc += __shfl_xor_sync(0xffffffffu, pc, 4);
                    pd += __shfl_xor_sync(0xffffffffu, pd, 4);
                    mx = fmaxf(mx, fmaxf(pc, pd));
                    sum += pc + pd;
                }
            }
            if (act && sl == 0) sM[n] = mx - sum * (1.0f / Uc);
        }
    }
    __syncthreads();

    // ---- phase 3: top-30 via parallel rank counting (ties -> lowest index) ----
    if (tid < Nc) {
        float mi = sM[tid];
        int rank = 0;
        for (int j = 0; j < Nc; j++) {
            float mj = sM[j];   // broadcast read
            rank += (mj > mi) || (mj == mi && j < tid) ? 1 : 0;
        }
        if (rank < Uc) { sRank[tid] = rank; sSel[rank] = tid; }
    }
    __syncthreads();

    // ---- phase 4: gather selected queries + V column-sum partials ----
    for (int i = tid; i < Uc * Dc; i += NT) {
        int u = i >> 6, d = i & 63;
        sQ[u * Dc + d] = Q[base + (size_t)sSel[u] * Dc + d];
    }
    {   // warp w sums rows [22w, 22w+22)
        int n0 = warp * 22, n1 = min(Nc, n0 + 22);
        float m0 = 0.f, m1 = 0.f;
        for (int n = n0; n < n1; n++) {
            m0 += sV[n * VS + lane];
            m1 += sV[n * VS + lane + 32];
        }
        sRed[warp * 64 + lane]      = m0;
        sRed[warp * 64 + lane + 32] = m1;
    }
    __syncthreads();

    // ---- mean combine (warps 0-1; consumed only after final barrier) ----
    if (tid < Dc) {
        float s = 0.f;
#pragma unroll
        for (int k = 0; k < NW; k++) s += sRed[k * 64 + tid];
        sMean[tid] = s * (1.0f / Nc);
    }

    // ---- phase 5+8 fused (barrier-free per warp): scores -> softmax -> GEMV ----
    {
        const int u0 = warp, u1 = warp + NW;
        const int half = lane >> 4;         // 0 or 1
        const int lsub = lane & 15;
        const int d0 = half << 5;           // 0 or 32

        float4 qa[8], qb[8];
        const float4* qa4 = (const float4*)&sQ[u0 * Dc + d0];
        const float4* qb4 = (const float4*)&sQ[u1 * Dc + d0];
#pragma unroll
        for (int j = 0; j < 8; j++) { qa[j] = qa4[j]; qb[j] = qb4[j]; }

        // --- scores: lane pairs (l, l+16) split d; each K row read once/warp ---
        float e0r[NSTEP], e1r[NSTEP];
        float lmax0 = -INFINITY, lmax1 = -INFINITY;
#pragma unroll
        for (int t = 0; t < NSTEP; t++) {
            int bn  = t * 32;
            int alo = min(bn + lsub,      Nc - 1) * KVS + d0;
            int ahi = min(bn + 16 + lsub, Nc - 1) * KVS + d0;
            const float4* klo = (const float4*)&sK[alo];
            const float4* khi = (const float4*)&sK[ahi];
            float p00 = 0.f, p01 = 0.f, p10 = 0.f, p11 = 0.f;
#pragma unroll
            for (int j = 0; j < 8; j++) {
                float4 kl = klo[j], kh = khi[j];
                p00 += dot4(qa[j], kl);
                p01 += dot4(qb[j], kl);
                p10 += dot4(qa[j], kh);
                p11 += dot4(qb[j], kh);
            }
            p00 += __shfl_xor_sync(0xffffffffu, p00, 16);
            p01 += __shfl_xor_sync(0xffffffffu, p01, 16);
            p10 += __shfl_xor_sync(0xffffffffu, p10, 16);
            p11 += __shfl_xor_sync(0xffffffffu, p11, 16);
            int n = bn + lane;
            float s0 = (half ? p10 : p00) * 0.125f;
            float s1 = (half ? p11 : p01) * 0.125f;
            bool ok = (n < Nc);
            e0r[t] = s0; e1r[t] = s1;
            lmax0 = fmaxf(lmax0, ok ? s0 : -INFINITY);
            lmax1 = fmaxf(lmax1, ok ? s1 : -INFINITY);
        }
#pragma unroll
        for (int o = 16; o > 0; o >>= 1) {
            lmax0 = fmaxf(lmax0, __shfl_xor_sync(0xffffffffu, lmax0, o));
            lmax1 = fmaxf(lmax1, __shfl_xor_sync(0xffffffffu, lmax1, o));
        }
        // --- exp + stage e-values to SMEM (zero beyond Nc) ---
        float lsum0 = 0.f, lsum1 = 0.f;
#pragma unroll
        for (int t = 0; t < NSTEP; t++) {
            int n = t * 32 + lane;
            bool ok = n < Nc;
            float e0 = ok ? __expf(e0r[t] - lmax0) : 0.f;
            float e1 = ok ? __expf(e1r[t] - lmax1) : 0.f;
            lsum0 += e0; lsum1 += e1;
            if (n < SCS) {
                sS[u0 * SCS + n] = e0;
                sS[u1 * SCS + n] = e1;
            }
        }
#pragma unroll
        for (int o = 16; o > 0; o >>= 1) {
            lsum0 += __shfl_xor_sync(0xffffffffu, lsum0, o);
            lsum1 += __shfl_xor_sync(0xffffffffu, lsum1, o);
        }
        float inv0 = 1.0f / lsum0;
        float inv1 = 1.0f / lsum1;

        // --- GEMV: e broadcast from SMEM (float4), V scalar row-major.
        //     Rows 325..327 read past sV into sM (finite) and e there is 0. ---
        float a00 = 0.f, a01 = 0.f, a10 = 0.f, a11 = 0.f;
        const float4* e0p = (const float4*)&sS[u0 * SCS];
        const float4* e1p = (const float4*)&sS[u1 * SCS];
#pragma unroll 2
        for (int t = 0; t < SCS / 4; t++) {
            float4 e0 = e0p[t], e1 = e1p[t];
            const float* vb = &sV[(t * 4) * VS];
            float v00 = vb[lane],            v01 = vb[lane + 32];
            float v10 = vb[VS + lane],       v11 = vb[VS + lane + 32];
            float v20 = vb[2 * VS + lane],   v21 = vb[2 * VS + lane + 32];
            float v30 = vb[3 * VS + lane],   v31 = vb[3 * VS + lane + 32];
            a00 += e0.x * v00 + e0.y * v10 + e0.z * v20 + e0.w * v30;
            a01 += e0.x * v01 + e0.y * v11 + e0.z * v21 + e0.w * v31;
            a10 += e1.x * v00 + e1.y * v10 + e1.z * v20 + e1.w * v30;
            a11 += e1.x * v01 + e1.y * v11 + e1.z * v21 + e1.w * v31;
        }
        // --- write the two selected output rows directly (coalesced) ---
        {
            int n0s = sSel[u0], n1s = sSel[u1];
            size_t o0 = ((size_t)(bb * Nc + n0s) * Tc + tt) * (size_t)(Hc * Dc) + hh * Dc;
            size_t o1 = ((size_t)(bb * Nc + n1s) * Tc + tt) * (size_t)(Hc * Dc) + hh * Dc;
            out[o0 + lane]      = a00 * inv0;
            out[o0 + lane + 32] = a01 * inv0;
            out[o1 + lane]      = a10 * inv1;
            out[o1 + lane + 32] = a11 * inv1;
        }
    }
    __syncthreads();

    // ---- phase 9: write mean rows only (selected rows already written) ----
    {
        for (int i = tid; i < Nc * Dc / 4; i += NT) {
            int n = i >> 4, d4 = (i & 15) * 4;
            if (sRank[n] >= 0) continue;
            float4 v = *(float4*)&sMean[d4];
            size_t o = ((size_t)(bb * Nc + n) * Tc + tt) * (size_t)(Hc * Dc)
                     + hh * Dc + d4;
            *(float4*)&out[o] = v;
        }
    }
}

// ---------------- launch ----------------
extern "C" void kernel_launch(void* const* d_in, const int* in_sizes, int n_in,
                              void* d_out, int out_size) {
    const float* Q = (const float*)d_in[0];
    const float* K = (const float*)d_in[1];
    const float* V = (const float*)d_in[2];
    float* out = (float*)d_out;

    cudaFuncSetAttribute(probsparse_kernel,
                         cudaFuncAttributeMaxDynamicSharedMemorySize, SMEM_BYTES);

    idx_kernel<<<(Nc * 32 + 255) / 256, 256>>>();
    probsparse_kernel<<<Gc, NT, SMEM_BYTES>>>(Q, K, V, out);
}

// round 9
// speedup vs baseline: 1.1437x; 1.0493x over previous
#include <cuda_runtime.h>
#include <cstdint>
#include <math.h>

// ============================================================================
// ProbSparse attention: B=4,H=8,T=12,N=325,D=64, FACTOR=5 -> U=30
// out[b,n,t,h*64+d] = ctx[b,h,t,n,d]
// K (stride 68) + V (stride 64) resident via cp.async. P2/P5 use packed
// fma.rn.f32x2. P8 is an n-striped GEMM tile: 8 warps, 60 accs each,
// partials in the dead K region, combine pass writes selected rows.
// ============================================================================

#define Bc 4
#define Hc 8
#define Tc 12
#define Nc 325
#define Dc 64
#define Uc 30
#define Gc (Bc*Hc*Tc)      // 384 groups
#define NT 480             // threads per block (15 warps)
#define NW 15
#define KVS 68             // K row stride (bank-staggered for P5)
#define VS  64             // V row stride
#define SCS 328            // e-value row stride (f4-aligned; rows 325..327 = 0)
#define NSTEP 11           // ceil(325/32)
#define NPASS 6            // ceil(325/60) query passes in phase 2
#define NCHUNK 82          // SCS/4 four-row chunks in P8
#define NSTRIPE 8          // warps doing P8 stripes

// ---------------- shared memory layout (float offsets) ----------------
#define OFF_K    0                        // 22100 (aliased by P8 partials)
#define OFF_V    22100                    // 20800
#define OFF_M    42900                    // 328
#define OFF_S    43228                    // 30*328 = 9840
#define OFF_Q    53068                    // 1920
#define OFF_MEAN 54988                    // 64
#define OFF_RED  55052                    // 1024
#define OFF_SEL  56076                    // 32
#define OFF_RANK 56108                    // 328
#define OFF_INV  56436                    // 32
#define SMEM_FLOATS 56468
#define SMEM_BYTES (SMEM_FLOATS * 4)      // 225872 B <= 232448

__device__ int g_idx2[Nc * 32];           // padded to 32 ints/row for int4 loads

// ---------------- threefry2x32 (exact JAX schedule) ----------------
__device__ __forceinline__ uint32_t rotl32(uint32_t x, int r) {
    return (x << r) | (x >> (32 - r));
}

__device__ __forceinline__ void tf2x32(uint32_t k0, uint32_t k1,
                                       uint32_t x0, uint32_t x1,
                                       uint32_t& o0, uint32_t& o1) {
    uint32_t ks2 = k0 ^ k1 ^ 0x1BD11BDAu;
    x0 += k0; x1 += k1;
#define TF_R(r) { x0 += x1; x1 = rotl32(x1, r); x1 ^= x0; }
    TF_R(13) TF_R(15) TF_R(26) TF_R(6)   x0 += k1;  x1 += ks2 + 1u;
    TF_R(17) TF_R(29) TF_R(16) TF_R(24)  x0 += ks2; x1 += k0  + 2u;
    TF_R(13) TF_R(15) TF_R(26) TF_R(6)   x0 += k0;  x1 += k1  + 3u;
    TF_R(17) TF_R(29) TF_R(16) TF_R(24)  x0 += k1;  x1 += ks2 + 4u;
    TF_R(13) TF_R(15) TF_R(26) TF_R(6)   x0 += ks2; x1 += k0  + 5u;
#undef TF_R
    o0 = x0; o1 = x1;
}

// idx_sample = jax.random.randint(key(42), (325,30), 0, 325)  [verified bit-exact]
__global__ void idx_kernel() {
    int j = blockIdx.x * blockDim.x + threadIdx.x;
    if (j >= Nc * 32) return;
    int n = j >> 5, u = j & 31;
    if (u >= Uc) { g_idx2[j] = 0; return; }
    int flat = n * Uc + u;
    const uint32_t SPAN = 325u;
    const uint32_t MULT = 321u;  // (2^32) mod 325
    uint32_t a0, a1, b0, b1;
    tf2x32(0u, 42u, 0u, 0u, a0, a1);
    tf2x32(0u, 42u, 0u, 1u, b0, b1);
    uint32_t h0, h1, l0, l1;
    tf2x32(a0, a1, 0u, (uint32_t)flat, h0, h1);
    uint32_t hi = h0 ^ h1;
    tf2x32(b0, b1, 0u, (uint32_t)flat, l0, l1);
    uint32_t lo = l0 ^ l1;
    g_idx2[j] = (int)(((hi % SPAN) * MULT + (lo % SPAN)) % SPAN);
}

// ---------------- packed f32x2 helpers ----------------
__device__ __forceinline__ uint64_t pk(float lo, float hi) {
    uint64_t r;
    asm("mov.b64 %0, {%1, %2};" : "=l"(r) : "f"(lo), "f"(hi));
    return r;
}
__device__ __forceinline__ void fma2(uint64_t& d, uint64_t a, uint64_t b) {
    asm("fma.rn.f32x2 %0, %1, %2, %0;" : "+l"(d) : "l"(a), "l"(b));
}
__device__ __forceinline__ float upk_sum(uint64_t a) {
    float x, y;
    asm("mov.b64 {%0, %1}, %2;" : "=f"(x), "=f"(y) : "l"(a));
    return x + y;
}

__device__ __forceinline__ void cp_async16(uint32_t dst, const void* src) {
    asm volatile("cp.async.cg.shared.global [%0], [%1], 16;\n"
                 :: "r"(dst), "l"(src));
}

// ---------------- main fused kernel: one block per (b,h,t) group ----------------
__global__ __launch_bounds__(NT, 1)
void probsparse_kernel(const float* __restrict__ Q,
                       const float* __restrict__ K,
                       const float* __restrict__ V,
                       float* __restrict__ out) {
    extern __shared__ float sm[];
    float* sK    = sm + OFF_K;
    float* sP    = sm + OFF_K;     // P8 partials alias dead K region
    float* sV    = sm + OFF_V;
    float* sM    = sm + OFF_M;
    float* sS    = sm + OFF_S;
    float* sQ    = sm + OFF_Q;
    float* sMean = sm + OFF_MEAN;
    float* sRed  = sm + OFF_RED;
    int*   sSel  = (int*)(sm + OFF_SEL);
    int*   sRank = (int*)(sm + OFF_RANK);
    float* sInv  = sm + OFF_INV;

    const int g    = blockIdx.x;
    const int tid  = threadIdx.x;
    const int lane = tid & 31;
    const int warp = tid >> 5;
    const size_t base = (size_t)g * Nc * Dc;
    const int bb = g / (Hc * Tc);
    const int hh = (g / Tc) % Hc;
    const int tt = g % Tc;

    // ---- phase 1: stage K (stride 68) and V (stride 64) via cp.async ----
    {
        uint32_t sb = (uint32_t)__cvta_generic_to_shared(sm);
        const float4* K4 = (const float4*)(K + base);
        const float4* V4 = (const float4*)(V + base);
        for (int i = tid; i < Nc * Dc / 4; i += NT) {
            int n = i >> 4, d4 = i & 15;
            cp_async16(sb + (uint32_t)(OFF_K + n * KVS + d4 * 4) * 4u, K4 + i);
            cp_async16(sb + (uint32_t)(OFF_V) * 4u + (uint32_t)i * 16u, V4 + i);
        }
        asm volatile("cp.async.commit_group;\n");
        for (int i = tid; i < Nc; i += NT) sRank[i] = -1;
        asm volatile("cp.async.wait_group 0;\n" ::: "memory");
    }
    __syncthreads();

    // ========================================================================
    // phase 2: sparsity measure M[n] = max_u(qk) - mean_u(qk).
    // 8-lane subgroup per query; idx int4 prefetch; packed f32x2 FMAs.
    // ========================================================================
    {
        const int sub = lane >> 3;     // query slot 0..3 within warp
        const int sl  = lane & 7;      // lane within subgroup
#pragma unroll 1
        for (int p = 0; p < NPASS; p++) {
            int n = p * 60 + warp * 4 + sub;
            bool act = n < Nc;
            int nn = act ? n : Nc - 1;
            const float4* qr = (const float4*)(Q + base + (size_t)nn * Dc + sl * 8);
            float4 qA = qr[0], qB = qr[1];
            uint64_t q2[4];
            q2[0] = pk(qA.x, qA.y); q2[1] = pk(qA.z, qA.w);
            q2[2] = pk(qB.x, qB.y); q2[3] = pk(qB.z, qB.w);
            const int4* idxp4 = (const int4*)(g_idx2 + nn * 32);
            float mx = -INFINITY, sum = 0.f;
            int4 A = idxp4[0], B = idxp4[1];
#pragma unroll
            for (int c = 0; c < 8; c++) {
                int kA = A.x, kB = A.y, kC = A.z, kD = A.w;
                A = B;
                if (c + 2 < 8) B = idxp4[c + 2];
                {   // pair 1
                    const float4* krA = (const float4*)&sK[kA * KVS + sl * 8];
                    const float4* krB = (const float4*)&sK[kB * KVS + sl * 8];
                    float4 A0 = krA[0], A1 = krA[1];
                    float4 B0 = krB[0], B1 = krB[1];
                    uint64_t pa2 = 0, pb2 = 0;
                    fma2(pa2, q2[0], pk(A0.x, A0.y));
                    fma2(pa2, q2[1], pk(A0.z, A0.w));
                    fma2(pa2, q2[2], pk(A1.x, A1.y));
                    fma2(pa2, q2[3], pk(A1.z, A1.w));
                    fma2(pb2, q2[0], pk(B0.x, B0.y));
                    fma2(pb2, q2[1], pk(B0.z, B0.w));
                    fma2(pb2, q2[2], pk(B1.x, B1.y));
                    fma2(pb2, q2[3], pk(B1.z, B1.w));
                    float pa = upk_sum(pa2);
                    float pb = upk_sum(pb2);
                    pa += __shfl_xor_sync(0xffffffffu, pa, 1);
                    pb += __shfl_xor_sync(0xffffffffu, pb, 1);
                    pa += __shfl_xor_sync(0xffffffffu, pa, 2);
                    pb += __shfl_xor_sync(0xffffffffu, pb, 2);
                    pa += __shfl_xor_sync(0xffffffffu, pa, 4);
                    pb += __shfl_xor_sync(0xffffffffu, pb, 4);
                    mx = fmaxf(mx, fmaxf(pa, pb));
                    sum += pa + pb;
                }
                if (c < 7) {   // pair 2 (chunk 7 holds only samples 28,29)
                    const float4* krC = (const float4*)&sK[kC * KVS + sl * 8];
                    const float4* krD = (const float4*)&sK[kD * KVS + sl * 8];
                    float4 C0 = krC[0], C1 = krC[1];
                    float4 D0 = krD[0], D1 = krD[1];
                    uint64_t pc2 = 0, pd2 = 0;
                    fma2(pc2, q2[0], pk(C0.x, C0.y));
                    fma2(pc2, q2[1], pk(C0.z, C0.w));
                    fma2(pc2, q2[2], pk(C1.x, C1.y));
                    fma2(pc2, q2[3], pk(C1.z, C1.w));
                    fma2(pd2, q2[0], pk(D0.x, D0.y));
                    fma2(pd2, q2[1], pk(D0.z, D0.w));
                    fma2(pd2, q2[2], pk(D1.x, D1.y));
                    fma2(pd2, q2[3], pk(D1.z, D1.w));
                    float pc = upk_sum(pc2);
                    float pd = upk_sum(pd2);
                    pc += __shfl_xor_sync(0xffffffffu, pc, 1);
                    pd += __shfl_xor_sync(0xffffffffu, pd, 1);
                    pc += __shfl_xor_sync(0xffffffffu, pc, 2);
                    pd += __shfl_xor_sync(0xffffffffu, pd, 2);
                    pc += __shfl_xor_sync(0xffffffffu, pc, 4);
                    pd += __shfl_xor_sync(0xffffffffu, pd, 4);
                    mx = fmaxf(mx, fmaxf(pc, pd));
                    sum += pc + pd;
                }
            }
            if (act && sl == 0) sM[n] = mx - sum * (1.0f / Uc);
        }
    }
    __syncthreads();

    // ---- phase 3: top-30 via parallel rank counting (ties -> lowest index) ----
    if (tid < Nc) {
        float mi = sM[tid];
        int rank = 0;
        for (int j = 0; j < Nc; j++) {
            float mj = sM[j];   // broadcast read
            rank += (mj > mi) || (mj == mi && j < tid) ? 1 : 0;
        }
        if (rank < Uc) { sRank[tid] = rank; sSel[rank] = tid; }
    }
    __syncthreads();

    // ---- phase 4: gather selected queries + V column-sum partials ----
    for (int i = tid; i < Uc * Dc; i += NT) {
        int u = i >> 6, d = i & 63;
        sQ[u * Dc + d] = Q[base + (size_t)sSel[u] * Dc + d];
    }
    {   // warp w sums rows [22w, 22w+22)
        int n0 = warp * 22, n1 = min(Nc, n0 + 22);
        float m0 = 0.f, m1 = 0.f;
        for (int n = n0; n < n1; n++) {
            m0 += sV[n * VS + lane];
            m1 += sV[n * VS + lane + 32];
        }
        sRed[warp * 64 + lane]      = m0;
        sRed[warp * 64 + lane + 32] = m1;
    }
    __syncthreads();

    // ---- mean combine (threads 0-63; consumed after final barrier) ----
    if (tid < Dc) {
        float s = 0.f;
#pragma unroll
        for (int k = 0; k < NW; k++) s += sRed[k * 64 + tid];
        sMean[tid] = s * (1.0f / Nc);
    }

    // ---- phase 5: scores + softmax (warp-pair u's; packed f32x2) ----
    {
        const int u0 = warp, u1 = warp + NW;
        const int half = lane >> 4;         // 0 or 1
        const int lsub = lane & 15;
        const int d0 = half << 5;           // 0 or 32

        uint64_t qa2[16], qb2[16];
        const float4* qa4 = (const float4*)&sQ[u0 * Dc + d0];
        const float4* qb4 = (const float4*)&sQ[u1 * Dc + d0];
#pragma unroll
        for (int j = 0; j < 8; j++) {
            float4 a = qa4[j], b = qb4[j];
            qa2[2 * j]     = pk(a.x, a.y);
            qa2[2 * j + 1] = pk(a.z, a.w);
            qb2[2 * j]     = pk(b.x, b.y);
            qb2[2 * j + 1] = pk(b.z, b.w);
        }

        float e0r[NSTEP], e1r[NSTEP];
        float lmax0 = -INFINITY, lmax1 = -INFINITY;
#pragma unroll
        for (int t = 0; t < NSTEP; t++) {
            int bn  = t * 32;
            int alo = min(bn + lsub,      Nc - 1) * KVS + d0;
            int ahi = min(bn + 16 + lsub, Nc - 1) * KVS + d0;
            const float4* klo = (const float4*)&sK[alo];
            const float4* khi = (const float4*)&sK[ahi];
            uint64_t p00 = 0, p01 = 0, p10 = 0, p11 = 0;
#pragma unroll
            for (int j = 0; j < 8; j++) {
                float4 kl = klo[j], kh = khi[j];
                uint64_t kl0 = pk(kl.x, kl.y), kl1 = pk(kl.z, kl.w);
                uint64_t kh0 = pk(kh.x, kh.y), kh1 = pk(kh.z, kh.w);
                fma2(p00, qa2[2 * j], kl0); fma2(p00, qa2[2 * j + 1], kl1);
                fma2(p01, qb2[2 * j], kl0); fma2(p01, qb2[2 * j + 1], kl1);
                fma2(p10, qa2[2 * j], kh0); fma2(p10, qa2[2 * j + 1], kh1);
                fma2(p11, qb2[2 * j], kh0); fma2(p11, qb2[2 * j + 1], kh1);
            }
            float s00 = upk_sum(p00), s01 = upk_sum(p01);
            float s10 = upk_sum(p10), s11 = upk_sum(p11);
            s00 += __shfl_xor_sync(0xffffffffu, s00, 16);
            s01 += __shfl_xor_sync(0xffffffffu, s01, 16);
            s10 += __shfl_xor_sync(0xffffffffu, s10, 16);
            s11 += __shfl_xor_sync(0xffffffffu, s11, 16);
            int n = bn + lane;
            float s0 = (half ? s10 : s00) * 0.125f;
            float s1 = (half ? s11 : s01) * 0.125f;
            bool ok = (n < Nc);
            e0r[t] = s0; e1r[t] = s1;
            lmax0 = fmaxf(lmax0, ok ? s0 : -INFINITY);
            lmax1 = fmaxf(lmax1, ok ? s1 : -INFINITY);
        }
#pragma unroll
        for (int o = 16; o > 0; o >>= 1) {
            lmax0 = fmaxf(lmax0, __shfl_xor_sync(0xffffffffu, lmax0, o));
            lmax1 = fmaxf(lmax1, __shfl_xor_sync(0xffffffffu, lmax1, o));
        }
        float lsum0 = 0.f, lsum1 = 0.f;
#pragma unroll
        for (int t = 0; t < NSTEP; t++) {
            int n = t * 32 + lane;
            bool ok = n < Nc;
            float e0 = ok ? __expf(e0r[t] - lmax0) : 0.f;
            float e1 = ok ? __expf(e1r[t] - lmax1) : 0.f;
            lsum0 += e0; lsum1 += e1;
            if (n < SCS) {
                sS[u0 * SCS + n] = e0;
                sS[u1 * SCS + n] = e1;
            }
        }
#pragma unroll
        for (int o = 16; o > 0; o >>= 1) {
            lsum0 += __shfl_xor_sync(0xffffffffu, lsum0, o);
            lsum1 += __shfl_xor_sync(0xffffffffu, lsum1, o);
        }
        if (lane == 0) {
            sInv[u0] = 1.0f / lsum0;
            sInv[u1] = 1.0f / lsum1;
        }
    }
    __syncthreads();   // sS + sInv complete; K now dead

    // ========================================================================
    // phase 8: n-striped GEMM tile. Warps 0..7 take interleaved 4-row chunks;
    // each chunk's V rows are read once and serve ALL 30 u (60 accs/lane).
    // Partials land in the dead K region.
    // ========================================================================
    if (warp < NSTRIPE) {
        float acc[60];
#pragma unroll
        for (int i = 0; i < 60; i++) acc[i] = 0.f;
#pragma unroll 1
        for (int c = warp; c < NCHUNK; c += NSTRIPE) {
            // V rows 4c..4c+3 (rows 325..327 read into sM region: finite, e=0)
            const float* vb = &sV[(c * 4) * VS];
            float v00 = vb[lane],            v01 = vb[lane + 32];
            float v10 = vb[VS + lane],       v11 = vb[VS + lane + 32];
            float v20 = vb[2 * VS + lane],   v21 = vb[2 * VS + lane + 32];
            float v30 = vb[3 * VS + lane],   v31 = vb[3 * VS + lane + 32];
#pragma unroll
            for (int u = 0; u < Uc; u++) {
                float4 e = ((const float4*)(sS + u * SCS))[c];   // broadcast
                acc[2 * u]     += e.x * v00 + e.y * v10 + e.z * v20 + e.w * v30;
                acc[2 * u + 1] += e.x * v01 + e.y * v11 + e.z * v21 + e.w * v31;
            }
        }
#pragma unroll
        for (int u = 0; u < Uc; u++) {
            sP[warp * (Uc * Dc) + u * Dc + lane]      = acc[2 * u];
            sP[warp * (Uc * Dc) + u * Dc + lane + 32] = acc[2 * u + 1];
        }
    }
    __syncthreads();

    // ---- combine partials -> selected rows; then mean rows ----
    for (int e = tid; e < Uc * Dc; e += NT) {
        int u = e >> 6, d = e & 63;
        float s = 0.f;
#pragma unroll
        for (int w = 0; w < NSTRIPE; w++) s += sP[w * (Uc * Dc) + e];
        s *= sInv[u];
        int n = sSel[u];
        out[((size_t)(bb * Nc + n) * Tc + tt) * (size_t)(Hc * Dc) + hh * Dc + d] = s;
    }
    for (int i = tid; i < Nc * Dc / 4; i += NT) {
        int n = i >> 4, d4 = (i & 15) * 4;
        if (sRank[n] >= 0) continue;
        float4 v = *(float4*)&sMean[d4];
        size_t o = ((size_t)(bb * Nc + n) * Tc + tt) * (size_t)(Hc * Dc)
                 + hh * Dc + d4;
        *(float4*)&out[o] = v;
    }
}

// ---------------- launch ----------------
extern "C" void kernel_launch(void* const* d_in, const int* in_sizes, int n_in,
                              void* d_out, int out_size) {
    const float* Q = (const float*)d_in[0];
    const float* K = (const float*)d_in[1];
    const float* V = (const float*)d_in[2];
    float* out = (float*)d_out;

    cudaFuncSetAttribute(probsparse_kernel,
                         cudaFuncAttributeMaxDynamicSharedMemorySize, SMEM_BYTES);

    idx_kernel<<<(Nc * 32 + 255) / 256, 256>>>();
    probsparse_kernel<<<Gc, NT, SMEM_BYTES>>>(Q, K, V, out);
}